// round 3
// baseline (speedup 1.0000x reference)
#include <cuda_runtime.h>
#include <cstdint>

// Scratch for raw int indices (pack kernel consumes them).
__device__ int g_idxs[8192];

// Component j of the value vector is controlled by bit SHUF[j] of the sign
// field; SHUF = {0,4,1,5,2,6,3,7}  ->  c_BIT[j] = 1 << SHUF[j].
__device__ __constant__ int c_BIT[8] = {1<<0, 1<<4, 1<<1, 1<<5, 1<<2, 1<<6, 1<<3, 1<<7};

__global__ void __launch_bounds__(256) e8p_quant_kernel(
    const float* __restrict__ X,
    const float* __restrict__ grid,
    const float* __restrict__ grid_norm,
    float* __restrict__ out)
{
    // Abs-code table: a[A] = grid[A<<8] (signs=0, p=0 row), plus its norm.
    __shared__ float s_a[256][9];      // stride 9 -> conflict-free LDS
    __shared__ float s_norm[256];

    int tid = threadIdx.x;
    for (int A = tid; A < 256; A += blockDim.x) {
        const float* g = grid + ((size_t)A << 11);   // (A<<8) * 8 floats
        #pragma unroll
        for (int j = 0; j < 8; j++) s_a[A][j] = g[j];
        s_norm[A] = grid_norm[A << 8];
    }
    __syncthreads();

    int warp = tid >> 5, lane = tid & 31;
    int row  = blockIdx.x * 8 + warp;                // 1024 blocks * 8 warps = 8192 rows

    const float* xr = X + (size_t)row * 8;
    float x[8];
    float sx = 0.f;
    #pragma unroll
    for (int j = 0; j < 8; j++) { x[j] = xr[j]; sx += x[j]; }
    const float p1_const = -0.5f * sx - 0.5f;

    float best = -1e30f;
    int bestc = 0x7fffffff;

    #pragma unroll 1
    for (int k = 0; k < 8; k++) {
        int A = lane + (k << 5);
        float a[8];
        #pragma unroll
        for (int j = 0; j < 8; j++) a[j] = s_a[A][j];
        float na = s_norm[A];

        // ---- p = 0: maximize 2*sum(sigma_j * x_j * a_j) - |a|^2, even #neg
        {
            float S = 0.f, mn = 1e30f;
            unsigned m = 0, mnbit = 0; int par = 0;
            #pragma unroll
            for (int j = 0; j < 8; j++) {
                float t  = x[j] * a[j];
                float at = fabsf(t);
                S += at;
                if (t < 0.f) { m ^= (unsigned)c_BIT[j]; par ^= 1; }
                if (at < mn) { mn = at; mnbit = (unsigned)c_BIT[j]; }
            }
            if (par) { S -= 2.f * mn; m ^= mnbit; }
            float sc = 2.f * S - na;
            int c = (A << 8) | (int)m;
            if (sc > best || (sc == best && c < bestc)) { best = sc; bestc = c; }
        }
        // ---- p = 1: u_j = a_j*(x_j + 0.25); score = 2*S' - |a|^2 - 0.5*sum(x) - 0.5
        {
            float S = 0.f, mn = 1e30f;
            unsigned m = 0, mnbit = 0; int par = 0;
            #pragma unroll
            for (int j = 0; j < 8; j++) {
                float t  = (x[j] + 0.25f) * a[j];
                float at = fabsf(t);
                S += at;
                if (t < 0.f) { m ^= (unsigned)c_BIT[j]; par ^= 1; }
                if (at < mn) { mn = at; mnbit = (unsigned)c_BIT[j]; }
            }
            if (par) { S -= 2.f * mn; m ^= mnbit; }
            float sc = 2.f * S - na + p1_const;
            int c = (A << 8) | ((int)m ^ 1);          // p=1 flips sign-field bit 0
            if (sc > best || (sc == best && c < bestc)) { best = sc; bestc = c; }
        }
    }

    // Warp argmax reduction; ties -> lowest code (matches jnp.argmax first-max).
    #pragma unroll
    for (int off = 16; off; off >>= 1) {
        float ob = __shfl_xor_sync(0xffffffffu, best, off);
        int   oc = __shfl_xor_sync(0xffffffffu, bestc, off);
        if (ob > best || (ob == best && oc < bestc)) { best = ob; bestc = oc; }
    }
    bestc = __shfl_sync(0xffffffffu, bestc, 0);

    if (lane < 8) {
        // vals = grid[idx] : out[0 .. 65535]
        out[(size_t)row * 8 + lane] = grid[(size_t)bestc * 8 + lane];
    }
    if (lane == 0) {
        out[65536 + row] = (float)bestc;             // idxs : out[65536 .. 73727]
        g_idxs[row] = bestc;
    }
}

// _pack_idxs under the reference's ACTUAL (int32, x64-disabled) semantics:
//   sign32 << 32  ->  0   (XLA saturates out-of-range shl to zero)
//   packed = int32 wraparound of abs32 byte-pack.
__global__ void e8p_pack_kernel(float* __restrict__ out)
{
    int L = blockIdx.x * blockDim.x + threadIdx.x;   // 0..2047
    int d = L & 3, b = (L >> 2) & 7, c = (L >> 5) & 3, a = L >> 7;
    int i = (a << 3) + b;    // 0..127  (row pair index)
    int j = (c << 2) + d;    // 0..15   (col pair index)

    int q00 = g_idxs[(2 * i)     * 32 + 2 * j];
    int q10 = g_idxs[(2 * i + 1) * 32 + 2 * j];
    int q01 = g_idxs[(2 * i)     * 32 + 2 * j + 1];
    int q11 = g_idxs[(2 * i + 1) * 32 + 2 * j + 1];

    unsigned abs32 = (unsigned)(q00 >> 8)
                   | ((unsigned)(q10 >> 8) << 8)
                   | ((unsigned)(q01 >> 8) << 16)
                   | ((unsigned)(q11 >> 8) << 24);

    out[73728 + L] = (float)(int)abs32;              // int32 wrap, then f32 cast
}

extern "C" void kernel_launch(void* const* d_in, const int* in_sizes, int n_in,
                              void* d_out, int out_size)
{
    const float* X         = (const float*)d_in[0];   // 256*32*8 = 65536
    const float* grid      = (const float*)d_in[1];   // 65536*8
    const float* grid_norm = (const float*)d_in[2];   // 65536
    float* out = (float*)d_out;                       // [vals | idxs | packed] fp32

    e8p_quant_kernel<<<1024, 256>>>(X, grid, grid_norm, out);
    e8p_pack_kernel<<<8, 256>>>(out);
}

// round 4
// speedup vs baseline: 1.1530x; 1.1530x over previous
#include <cuda_runtime.h>
#include <cstdint>

// Scratch for raw int indices (pack epilogue consumes them) + completion ticket.
__device__ int g_idxs[8192];
__device__ unsigned g_done = 0;   // must be 0 at entry of every replay; last block resets it

__global__ void __launch_bounds__(256) e8p_fused_kernel(
    const float* __restrict__ X,
    const float* __restrict__ grid,
    const float* __restrict__ grid_norm,
    float* __restrict__ out)
{
    // Abs-code table: a[A] = grid[A<<8] (signs=0, p=0 row), plus its norm.
    __shared__ __align__(16) float s_a[256][8];   // float4-loadable
    __shared__ float s_norm[256];
    __shared__ unsigned s_ticket;

    const int tid = threadIdx.x;
    for (int A = tid; A < 256; A += 256) {
        const float4* g4 = reinterpret_cast<const float4*>(grid + ((size_t)A << 11));
        float4* d4 = reinterpret_cast<float4*>(s_a[A]);
        d4[0] = g4[0];
        d4[1] = g4[1];
        s_norm[A] = grid_norm[A << 8];
    }
    __syncthreads();

    const int warp = tid >> 5, lane = tid & 31;
    const int row  = blockIdx.x * 8 + warp;          // 1024 blocks * 8 warps = 8192 rows

    const float* xr = X + (size_t)row * 8;
    float x[8], x25[8];
    #pragma unroll
    for (int j = 0; j < 8; j++) { x[j] = xr[j]; x25[j] = x[j] + 0.25f; }
    float sx = 0.f;
    #pragma unroll
    for (int j = 0; j < 8; j++) sx += x[j];
    const float p1_const = -0.5f * sx - 0.5f;

    // Component j of the value vector <- bit SHUF[j] of the sign field.
    // SHUF = {0,4,1,5,2,6,3,7} -> BITS[j] = 1 << SHUF[j].
    constexpr unsigned BITS[8] = {1u<<0, 1u<<4, 1u<<1, 1u<<5, 1u<<2, 1u<<6, 1u<<3, 1u<<7};

    float best = -1e30f;
    int bestc = 0x7fffffff;

    #pragma unroll 1
    for (int k = 0; k < 8; k++) {
        const int A = lane + (k << 5);
        float a[8];
        {
            const float4* p = reinterpret_cast<const float4*>(s_a[A]);
            float4 a0 = p[0], a1 = p[1];
            a[0]=a0.x; a[1]=a0.y; a[2]=a0.z; a[3]=a0.w;
            a[4]=a1.x; a[5]=a1.y; a[6]=a1.z; a[7]=a1.w;
        }
        const float na = s_norm[A];

        // ---- p = 0: maximize 2*sum(sigma_j * x_j * a_j) - |a|^2, even #neg
        {
            float S = 0.f, mn = 1e30f;
            unsigned m = 0, mnbit = 0;
            #pragma unroll
            for (int j = 0; j < 8; j++) {
                float t = x[j] * a[j];
                unsigned sgn = (unsigned)((int)__float_as_uint(t) >> 31); // all-ones if neg
                m |= sgn & BITS[j];
                float at = fabsf(t);
                S += at;
                bool pr = at < mn;                 // strict: keep first min (exact)
                mnbit = pr ? BITS[j] : mnbit;
                mn    = pr ? at : mn;
            }
            if (__popc(m) & 1) { S -= 2.f * mn; m ^= mnbit; }
            float sc = 2.f * S - na;
            int c = (A << 8) | (int)m;
            if (sc > best || (sc == best && c < bestc)) { best = sc; bestc = c; }
        }
        // ---- p = 1: u_j = a_j*(x_j + 0.25); score = 2*S' - |a|^2 - 0.5*sum(x) - 0.5
        {
            float S = 0.f, mn = 1e30f;
            unsigned m = 0, mnbit = 0;
            #pragma unroll
            for (int j = 0; j < 8; j++) {
                float t = x25[j] * a[j];
                unsigned sgn = (unsigned)((int)__float_as_uint(t) >> 31);
                m |= sgn & BITS[j];
                float at = fabsf(t);
                S += at;
                bool pr = at < mn;
                mnbit = pr ? BITS[j] : mnbit;
                mn    = pr ? at : mn;
            }
            if (__popc(m) & 1) { S -= 2.f * mn; m ^= mnbit; }
            float sc = 2.f * S - na + p1_const;
            int c = (A << 8) | ((int)m ^ 1);       // p=1 flips sign-field bit 0
            if (sc > best || (sc == best && c < bestc)) { best = sc; bestc = c; }
        }
    }

    // Warp argmax reduction; ties -> lowest code (matches jnp.argmax first-max).
    #pragma unroll
    for (int off = 16; off; off >>= 1) {
        float ob = __shfl_xor_sync(0xffffffffu, best, off);
        int   oc = __shfl_xor_sync(0xffffffffu, bestc, off);
        if (ob > best || (ob == best && oc < bestc)) { best = ob; bestc = oc; }
    }
    bestc = __shfl_sync(0xffffffffu, bestc, 0);

    if (lane < 8) {
        // vals = grid[idx] : out[0 .. 65535]
        out[(size_t)row * 8 + lane] = grid[(size_t)bestc * 8 + lane];
    }
    if (lane == 0) {
        out[65536 + row] = (float)bestc;             // idxs : out[65536 .. 73727]
        g_idxs[row] = bestc;
    }

    // ---- Last-block epilogue: _pack_idxs (int32 / x64-disabled semantics:
    //      sign32 << 32 saturates to 0 in XLA; packed = int32 wrap of abs32).
    __syncthreads();
    if (tid == 0) {
        __threadfence();                              // publish g_idxs
        s_ticket = atomicAdd(&g_done, 1u);
    }
    __syncthreads();
    if (s_ticket == gridDim.x - 1) {                  // last arriving block
        __threadfence();                              // acquire everyone's g_idxs
        for (int L = tid; L < 2048; L += 256) {
            int d = L & 3, b = (L >> 2) & 7, c = (L >> 5) & 3, aa = L >> 7;
            int i = (aa << 3) + b;    // 0..127  (row-pair index)
            int j = (c << 2) + d;     // 0..15   (col-pair index)

            int q00 = g_idxs[(2 * i)     * 32 + 2 * j];
            int q10 = g_idxs[(2 * i + 1) * 32 + 2 * j];
            int q01 = g_idxs[(2 * i)     * 32 + 2 * j + 1];
            int q11 = g_idxs[(2 * i + 1) * 32 + 2 * j + 1];

            unsigned abs32 = (unsigned)(q00 >> 8)
                           | ((unsigned)(q10 >> 8) << 8)
                           | ((unsigned)(q01 >> 8) << 16)
                           | ((unsigned)(q11 >> 8) << 24);

            out[73728 + L] = (float)(int)abs32;       // int32 wrap, then f32 cast
        }
        __syncthreads();
        if (tid == 0) g_done = 0;                     // reset for next graph replay
    }
}

extern "C" void kernel_launch(void* const* d_in, const int* in_sizes, int n_in,
                              void* d_out, int out_size)
{
    const float* X         = (const float*)d_in[0];   // 256*32*8 = 65536
    const float* grid      = (const float*)d_in[1];   // 65536*8
    const float* grid_norm = (const float*)d_in[2];   // 65536
    float* out = (float*)d_out;                       // [vals | idxs | packed] fp32

    e8p_fused_kernel<<<1024, 256>>>(X, grid, grid_norm, out);
}

// round 5
// speedup vs baseline: 1.5405x; 1.3361x over previous
#include <cuda_runtime.h>
#include <cstdint>

// Scratch for raw int indices (pack epilogue consumes them) + completion ticket.
__device__ int g_idxs[8192];
__device__ unsigned g_done = 0;   // 0 at entry of every replay; last block resets it

__global__ void __launch_bounds__(256, 5) e8p_fused_kernel(
    const float* __restrict__ X,
    const float* __restrict__ grid,
    const float* __restrict__ grid_norm,
    float* __restrict__ out)
{
    // Abs-code table: a[A] = grid[A<<8], stride 12 floats (48B) -> LDS.128 conflict-free.
    __shared__ __align__(16) float s_a[256][12];
    __shared__ float s_norm[256];
    __shared__ unsigned s_ticket;

    const int tid = threadIdx.x;
    {
        const int A = tid;                            // exactly 256 threads
        const float4* g4 = reinterpret_cast<const float4*>(grid + ((size_t)A << 11));
        float4* d4 = reinterpret_cast<float4*>(s_a[A]);
        d4[0] = g4[0];
        d4[1] = g4[1];
        s_norm[A] = grid_norm[A << 8];
    }
    __syncthreads();

    const int warp = tid >> 5, lane = tid & 31;
    const int row  = blockIdx.x * 8 + warp;           // 1024 blocks * 8 warps = 8192 rows

    float x[8], x25[8];
    {
        const float4* xr4 = reinterpret_cast<const float4*>(X + (size_t)row * 8);
        float4 v0 = xr4[0], v1 = xr4[1];
        x[0]=v0.x; x[1]=v0.y; x[2]=v0.z; x[3]=v0.w;
        x[4]=v1.x; x[5]=v1.y; x[6]=v1.z; x[7]=v1.w;
    }
    float sx = 0.f;
    #pragma unroll
    for (int j = 0; j < 8; j++) { x25[j] = x[j] + 0.25f; sx += x[j]; }
    const float p1c = -0.5f * sx - 0.5f;

    // Component j of the value vector <- bit SHUF[j] of the sign field.
    // SHUF = {0,4,1,5,2,6,3,7} -> BITS[j] = 1 << SHUF[j].
    constexpr unsigned BITS[8] = {1u<<0, 1u<<4, 1u<<1, 1u<<5, 1u<<2, 1u<<6, 1u<<3, 1u<<7};

    // Two independent best-chains (p=0 / p=1); cid = A (merged to (A<<1)|p later).
    float best0 = -1e30f, best1 = -1e30f;
    int cA0 = 0x7fffffff, cA1 = 0x7fffffff;

    #pragma unroll
    for (int k = 0; k < 8; k++) {
        const int A = lane + (k << 5);
        float a[8];
        {
            const float4* p4 = reinterpret_cast<const float4*>(s_a[A]);
            float4 a0 = p4[0], a1 = p4[1];
            a[0]=a0.x; a[1]=a0.y; a[2]=a0.z; a[3]=a0.w;
            a[4]=a1.x; a[5]=a1.y; a[6]=a1.z; a[7]=a1.w;
        }
        const float na = s_norm[A];

        // ---- p = 0: score = 2*(S - [parity]*2*mn) - |a|^2
        {
            float t[8];
            #pragma unroll
            for (int j = 0; j < 8; j++) t[j] = x[j] * a[j];
            int px = ((__float_as_int(t[0]) ^ __float_as_int(t[1])) ^
                      (__float_as_int(t[2]) ^ __float_as_int(t[3]))) ^
                     ((__float_as_int(t[4]) ^ __float_as_int(t[5])) ^
                      (__float_as_int(t[6]) ^ __float_as_int(t[7])));
            float S = ((fabsf(t[0]) + fabsf(t[1])) + (fabsf(t[2]) + fabsf(t[3])))
                    + ((fabsf(t[4]) + fabsf(t[5])) + (fabsf(t[6]) + fabsf(t[7])));
            float mn = fminf(fminf(fminf(fabsf(t[0]), fabsf(t[1])),
                                   fminf(fabsf(t[2]), fabsf(t[3]))),
                             fminf(fminf(fabsf(t[4]), fabsf(t[5])),
                                   fminf(fabsf(t[6]), fabsf(t[7]))));
            float Sadj = fmaf(-2.f, mn, S);
            float Sp = (px < 0) ? Sadj : S;           // sign of xor = parity of neg signs
            float sc = fmaf(2.f, Sp, -na);
            if (sc > best0) { best0 = sc; cA0 = A; }  // first-wins: lowest A on tie
        }
        // ---- p = 1: u_j = a_j*(x_j+0.25); score += p1c
        {
            float t[8];
            #pragma unroll
            for (int j = 0; j < 8; j++) t[j] = x25[j] * a[j];
            int px = ((__float_as_int(t[0]) ^ __float_as_int(t[1])) ^
                      (__float_as_int(t[2]) ^ __float_as_int(t[3]))) ^
                     ((__float_as_int(t[4]) ^ __float_as_int(t[5])) ^
                      (__float_as_int(t[6]) ^ __float_as_int(t[7])));
            float S = ((fabsf(t[0]) + fabsf(t[1])) + (fabsf(t[2]) + fabsf(t[3])))
                    + ((fabsf(t[4]) + fabsf(t[5])) + (fabsf(t[6]) + fabsf(t[7])));
            float mn = fminf(fminf(fminf(fabsf(t[0]), fabsf(t[1])),
                                   fminf(fabsf(t[2]), fabsf(t[3]))),
                             fminf(fminf(fabsf(t[4]), fabsf(t[5])),
                                   fminf(fabsf(t[6]), fabsf(t[7]))));
            float Sadj = fmaf(-2.f, mn, S);
            float Sp = (px < 0) ? Sadj : S;
            float sc = fmaf(2.f, Sp, -na) + p1c;      // same rounding order as R4
            if (sc > best1) { best1 = sc; cA1 = A; }
        }
    }

    // Merge parity chains: prefer p=0 on exact ties at same A; lower A on cross ties.
    float best; int cid;
    if (best1 > best0 || (best1 == best0 && cA1 < cA0)) { best = best1; cid = (cA1 << 1) | 1; }
    else                                                { best = best0; cid = (cA0 << 1); }

    // Warp argmax (butterfly, total order via cid tie-break -> all lanes converge).
    #pragma unroll
    for (int off = 16; off; off >>= 1) {
        float ob = __shfl_xor_sync(0xffffffffu, best, off);
        int   oc = __shfl_xor_sync(0xffffffffu, cid,  off);
        if (ob > best || (ob == best && oc < cid)) { best = ob; cid = oc; }
    }

    // Recompute full sign mask + argmin flip for the single winning candidate.
    const int Aw = cid >> 1, pw = cid & 1;
    int bestc;
    {
        const float* av = s_a[Aw];
        unsigned m = 0, mnbit = 0;
        float mnv = 1e30f;
        #pragma unroll
        for (int j = 0; j < 8; j++) {
            float xx = pw ? x25[j] : x[j];
            float t  = xx * av[j];
            unsigned sgn = (unsigned)(__float_as_int(t) >> 31);  // all-ones if neg
            m |= sgn & BITS[j];
            float at = fabsf(t);
            if (at < mnv) { mnv = at; mnbit = BITS[j]; }         // strict: first min
        }
        if (__popc(m) & 1) m ^= mnbit;
        bestc = (Aw << 8) | ((int)m ^ pw);            // p=1 flips sign-field bit 0
    }

    if (lane < 8) {
        // vals = grid[idx] : out[0 .. 65535]
        out[(size_t)row * 8 + lane] = grid[(size_t)bestc * 8 + lane];
    }
    if (lane == 0) {
        out[65536 + row] = (float)bestc;              // idxs : out[65536 .. 73727]
        g_idxs[row] = bestc;
    }

    // ---- Last-block epilogue: _pack_idxs (int32 / x64-disabled semantics:
    //      sign32 << 32 saturates to 0 in XLA; packed = int32 wrap of abs32).
    __syncthreads();
    if (tid == 0) {
        __threadfence();                              // publish g_idxs
        s_ticket = atomicAdd(&g_done, 1u);
    }
    __syncthreads();
    if (s_ticket == gridDim.x - 1) {                  // last arriving block
        __threadfence();                              // acquire everyone's g_idxs
        for (int L = tid; L < 2048; L += 256) {
            int d = L & 3, b = (L >> 2) & 7, c = (L >> 5) & 3, aa = L >> 7;
            int i = (aa << 3) + b;    // 0..127  (row-pair index)
            int j = (c << 2) + d;     // 0..15   (col-pair index)

            int q00 = g_idxs[(2 * i)     * 32 + 2 * j];
            int q10 = g_idxs[(2 * i + 1) * 32 + 2 * j];
            int q01 = g_idxs[(2 * i)     * 32 + 2 * j + 1];
            int q11 = g_idxs[(2 * i + 1) * 32 + 2 * j + 1];

            unsigned abs32 = (unsigned)(q00 >> 8)
                           | ((unsigned)(q10 >> 8) << 8)
                           | ((unsigned)(q01 >> 8) << 16)
                           | ((unsigned)(q11 >> 8) << 24);

            out[73728 + L] = (float)(int)abs32;       // int32 wrap, then f32 cast
        }
        __syncthreads();
        if (tid == 0) g_done = 0;                     // reset for next graph replay
    }
}

extern "C" void kernel_launch(void* const* d_in, const int* in_sizes, int n_in,
                              void* d_out, int out_size)
{
    const float* X         = (const float*)d_in[0];   // 256*32*8 = 65536
    const float* grid      = (const float*)d_in[1];   // 65536*8
    const float* grid_norm = (const float*)d_in[2];   // 65536
    float* out = (float*)d_out;                       // [vals | idxs | packed] fp32

    e8p_fused_kernel<<<1024, 256>>>(X, grid, grid_norm, out);
}

// round 6
// speedup vs baseline: 1.9613x; 1.2731x over previous
#include <cuda_runtime.h>
#include <cstdint>

// Block bk (0..1023): ipair = bk>>3 (row-pair of the 256x32 idx matrix),
// jg = bk&7 (column group of 4). Warp w handles entry
//   m = 2*ipair + (w>>2),  n = 4*jg + (w&3)   -> flat row r = m*32 + n.
// All 4 idx entries of each packed word live inside one block -> local pack.

__global__ void __launch_bounds__(256, 6) e8p_fused_kernel(
    const float* __restrict__ X,
    const float* __restrict__ grid,
    const float* __restrict__ grid_norm,
    float* __restrict__ out)
{
    // Abs-code table: a[A] = grid[A<<8], stride 12 floats (48B) -> LDS.128 conflict-free.
    __shared__ __align__(16) float s_a[256][12];
    __shared__ float s_norm[256];
    __shared__ int s_bestc[8];

    const int tid = threadIdx.x;
    {
        const int A = tid;                            // exactly 256 threads
        const float4* g4 = reinterpret_cast<const float4*>(grid + ((size_t)A << 11));
        float4* d4 = reinterpret_cast<float4*>(s_a[A]);
        d4[0] = g4[0];
        d4[1] = g4[1];
        s_norm[A] = grid_norm[A << 8];
    }
    __syncthreads();

    const int warp = tid >> 5, lane = tid & 31;
    const int ipair = blockIdx.x >> 3;                // 0..127
    const int jg    = blockIdx.x & 7;                 // 0..7
    const int m     = 2 * ipair + (warp >> 2);
    const int n     = 4 * jg + (warp & 3);
    const int row   = m * 32 + n;                     // flat entry 0..8191

    float x[8], x25[8];
    {
        const float4* xr4 = reinterpret_cast<const float4*>(X + (size_t)row * 8);
        float4 v0 = xr4[0], v1 = xr4[1];
        x[0]=v0.x; x[1]=v0.y; x[2]=v0.z; x[3]=v0.w;
        x[4]=v1.x; x[5]=v1.y; x[6]=v1.z; x[7]=v1.w;
    }
    float sx = 0.f;
    #pragma unroll
    for (int j = 0; j < 8; j++) { x25[j] = x[j] + 0.25f; sx += x[j]; }
    const float p1c = -0.5f * sx - 0.5f;

    // Component j of the value vector <- bit SHUF[j] of the sign field.
    // SHUF = {0,4,1,5,2,6,3,7} -> BITS[j] = 1 << SHUF[j].
    constexpr unsigned BITS[8] = {1u<<0, 1u<<4, 1u<<1, 1u<<5, 1u<<2, 1u<<6, 1u<<3, 1u<<7};

    // Two independent best-chains (p=0 / p=1); carries A only (code rebuilt for winner).
    float best0 = -1e30f, best1 = -1e30f;
    int cA0 = 0x7fffffff, cA1 = 0x7fffffff;

    #pragma unroll
    for (int k = 0; k < 8; k++) {
        const int A = lane + (k << 5);
        float a[8];
        {
            const float4* p4 = reinterpret_cast<const float4*>(s_a[A]);
            float4 a0 = p4[0], a1 = p4[1];
            a[0]=a0.x; a[1]=a0.y; a[2]=a0.z; a[3]=a0.w;
            a[4]=a1.x; a[5]=a1.y; a[6]=a1.z; a[7]=a1.w;
        }
        const float na = s_norm[A];

        // ---- p = 0: score = 2*(S - [parity]*2*mn) - |a|^2
        {
            float t[8];
            #pragma unroll
            for (int j = 0; j < 8; j++) t[j] = x[j] * a[j];
            int px = ((__float_as_int(t[0]) ^ __float_as_int(t[1])) ^
                      (__float_as_int(t[2]) ^ __float_as_int(t[3]))) ^
                     ((__float_as_int(t[4]) ^ __float_as_int(t[5])) ^
                      (__float_as_int(t[6]) ^ __float_as_int(t[7])));
            float S = ((fabsf(t[0]) + fabsf(t[1])) + (fabsf(t[2]) + fabsf(t[3])))
                    + ((fabsf(t[4]) + fabsf(t[5])) + (fabsf(t[6]) + fabsf(t[7])));
            float mn = fminf(fminf(fminf(fabsf(t[0]), fabsf(t[1])),
                                   fminf(fabsf(t[2]), fabsf(t[3]))),
                             fminf(fminf(fabsf(t[4]), fabsf(t[5])),
                                   fminf(fabsf(t[6]), fabsf(t[7]))));
            float Sadj = fmaf(-2.f, mn, S);
            float Sp = (px < 0) ? Sadj : S;           // sign of xor = parity of neg signs
            float sc = fmaf(2.f, Sp, -na);
            if (sc > best0) { best0 = sc; cA0 = A; }  // first-wins: lowest A on tie
        }
        // ---- p = 1: u_j = a_j*(x_j+0.25); score += p1c
        {
            float t[8];
            #pragma unroll
            for (int j = 0; j < 8; j++) t[j] = x25[j] * a[j];
            int px = ((__float_as_int(t[0]) ^ __float_as_int(t[1])) ^
                      (__float_as_int(t[2]) ^ __float_as_int(t[3]))) ^
                     ((__float_as_int(t[4]) ^ __float_as_int(t[5])) ^
                      (__float_as_int(t[6]) ^ __float_as_int(t[7])));
            float S = ((fabsf(t[0]) + fabsf(t[1])) + (fabsf(t[2]) + fabsf(t[3])))
                    + ((fabsf(t[4]) + fabsf(t[5])) + (fabsf(t[6]) + fabsf(t[7])));
            float mn = fminf(fminf(fminf(fabsf(t[0]), fabsf(t[1])),
                                   fminf(fabsf(t[2]), fabsf(t[3]))),
                             fminf(fminf(fabsf(t[4]), fabsf(t[5])),
                                   fminf(fabsf(t[6]), fabsf(t[7]))));
            float Sadj = fmaf(-2.f, mn, S);
            float Sp = (px < 0) ? Sadj : S;
            float sc = fmaf(2.f, Sp, -na) + p1c;      // same rounding order as before
            if (sc > best1) { best1 = sc; cA1 = A; }
        }
    }

    // Merge parity chains: prefer p=0 on exact ties at same A; lower A on cross ties.
    float best; int cid;
    if (best1 > best0 || (best1 == best0 && cA1 < cA0)) { best = best1; cid = (cA1 << 1) | 1; }
    else                                                { best = best0; cid = (cA0 << 1); }

    // Warp argmax (butterfly, total order via cid tie-break -> all lanes converge).
    #pragma unroll
    for (int off = 16; off; off >>= 1) {
        float ob = __shfl_xor_sync(0xffffffffu, best, off);
        int   oc = __shfl_xor_sync(0xffffffffu, cid,  off);
        if (ob > best || (ob == best && oc < cid)) { best = ob; cid = oc; }
    }

    // Recompute full sign mask + argmin flip for the single winning candidate.
    const int Aw = cid >> 1, pw = cid & 1;
    int bestc;
    {
        const float* av = s_a[Aw];
        unsigned mk = 0, mnbit = 0;
        float mnv = 1e30f;
        #pragma unroll
        for (int j = 0; j < 8; j++) {
            float xx = pw ? x25[j] : x[j];
            float t  = xx * av[j];
            unsigned sgn = (unsigned)(__float_as_int(t) >> 31);  // all-ones if neg
            mk |= sgn & BITS[j];
            float at = fabsf(t);
            if (at < mnv) { mnv = at; mnbit = BITS[j]; }         // strict: first min
        }
        if (__popc(mk) & 1) mk ^= mnbit;
        bestc = (Aw << 8) | ((int)mk ^ pw);           // p=1 flips sign-field bit 0
    }

    if (lane < 8) {
        // vals = grid[idx] : out[0 .. 65535]
        out[(size_t)row * 8 + lane] = grid[(size_t)bestc * 8 + lane];
    }
    if (lane == 0) {
        out[65536 + row] = (float)bestc;              // idxs : out[65536 .. 73727]
        s_bestc[warp] = bestc;
    }

    // ---- Block-local _pack_idxs (int32 / x64-disabled semantics: the reference's
    //      sign32 << 32 saturates to 0 in XLA; packed = int32 wrap of abs32).
    //      Packed word (i=ipair, j=2*jg+jj) needs q at (2i|2i+1, 2j|2j+1) — all
    //      8 of this block's entries; warp layout: w = (dm<<2)|dn, dn = n - 4*jg.
    __syncthreads();
    if (tid < 2) {
        const int jj = tid;                           // jj = 0,1
        const int j  = 2 * jg + jj;
        int q00 = s_bestc[      2 * jj    ];          // (dm=0, dn=2jj)   -> (2i,   2j)
        int q10 = s_bestc[4 +   2 * jj    ];          // (dm=1, dn=2jj)   -> (2i+1, 2j)
        int q01 = s_bestc[      2 * jj + 1];          // (dm=0, dn=2jj+1) -> (2i,   2j+1)
        int q11 = s_bestc[4 +   2 * jj + 1];          // (dm=1, dn=2jj+1) -> (2i+1, 2j+1)

        unsigned abs32 = (unsigned)(q00 >> 8)
                       | ((unsigned)(q10 >> 8) << 8)
                       | ((unsigned)(q01 >> 8) << 16)
                       | ((unsigned)(q11 >> 8) << 24);

        // L from (i, j): aa=i>>3, b=i&7, c=j>>2, d=j&3 -> L = aa<<7 | c<<5 | b<<2 | d
        const int i = ipair;
        const int L = ((i >> 3) << 7) | ((j >> 2) << 5) | ((i & 7) << 2) | (j & 3);
        out[73728 + L] = (float)(int)abs32;           // int32 wrap, then f32 cast
    }
}

extern "C" void kernel_launch(void* const* d_in, const int* in_sizes, int n_in,
                              void* d_out, int out_size)
{
    const float* X         = (const float*)d_in[0];   // 256*32*8 = 65536
    const float* grid      = (const float*)d_in[1];   // 65536*8
    const float* grid_norm = (const float*)d_in[2];   // 65536
    float* out = (float*)d_out;                       // [vals | idxs | packed] fp32

    e8p_fused_kernel<<<1024, 256>>>(X, grid, grid_norm, out);
}